// round 1
// baseline (speedup 1.0000x reference)
#include <cuda_runtime.h>
#include <math.h>

// ---------------- problem constants ----------------
#define BN    2
#define SQL   1024
#define DIM   2048
#define NH    16
#define HD    128
#define SP    1024
#define SS    1024
#define SMm   512
#define SKV   2560    // SP+SS+SMm
#define DP    1280
#define DS    1024
#define DMm   768
#define INNER 8192

// ---------------- scratch (no allocations allowed) ----------------
__device__ float g_xn [BN*SQL*DIM];      // rmsnormed input
__device__ float g_q  [BN*SQL*DIM];
__device__ float g_k  [BN*SKV*DIM];
__device__ float g_v  [BN*SKV*DIM];
__device__ float g_ctx[BN*SQL*DIM];
__device__ float g_h  [BN*SQL*DIM];      // residual after attention
__device__ float g_ln [BN*SQL*DIM];
__device__ float g_mid[BN*SQL*INNER];

// ---------------- RMSNorm ----------------
__global__ __launch_bounds__(256) void rms_kernel(
    const float* __restrict__ x, const float* __restrict__ w, float* __restrict__ y)
{
    __shared__ float red[256];
    int row = blockIdx.x;
    const float* xr = x + (size_t)row * DIM;
    float ss = 0.f;
    for (int c = threadIdx.x; c < DIM; c += 256) { float v = xr[c]; ss += v * v; }
    red[threadIdx.x] = ss; __syncthreads();
    for (int s = 128; s > 0; s >>= 1) {
        if (threadIdx.x < s) red[threadIdx.x] += red[threadIdx.x + s];
        __syncthreads();
    }
    float inv = rsqrtf(red[0] / (float)DIM + 1e-6f);
    float* yr = y + (size_t)row * DIM;
    for (int c = threadIdx.x; c < DIM; c += 256) yr[c] = xr[c] * inv * w[c];
}

// ---------------- LayerNorm ----------------
__global__ __launch_bounds__(256) void ln_kernel(
    const float* __restrict__ x, const float* __restrict__ g,
    const float* __restrict__ b, float* __restrict__ y)
{
    __shared__ float r1[256];
    __shared__ float r2[256];
    int row = blockIdx.x;
    const float* xr = x + (size_t)row * DIM;
    float s1 = 0.f, s2 = 0.f;
    for (int c = threadIdx.x; c < DIM; c += 256) { float v = xr[c]; s1 += v; s2 += v * v; }
    r1[threadIdx.x] = s1; r2[threadIdx.x] = s2; __syncthreads();
    for (int s = 128; s > 0; s >>= 1) {
        if (threadIdx.x < s) { r1[threadIdx.x] += r1[threadIdx.x + s]; r2[threadIdx.x] += r2[threadIdx.x + s]; }
        __syncthreads();
    }
    float mu  = r1[0] / (float)DIM;
    float var = r2[0] / (float)DIM - mu * mu;
    float rstd = rsqrtf(var + 1e-5f);
    float* yr = y + (size_t)row * DIM;
    for (int c = threadIdx.x; c < DIM; c += 256)
        yr[c] = (xr[c] - mu) * rstd * g[c] + b[c];
}

// ---------------- GEMM: C = A[M,K] @ W[K,N] (+epilogue) ----------------
// 128x128 block tile, 8x8 per-thread micro-tile, Ktile=8.
// epi: 0 = +bias
//      1 = res + tanh(*gate) * (acc + bias)         (Wo)
//      2 = gelu_exact(acc)                          (W1, no bias)
//      3 = res + tanh(*gate) * acc                  (W2, no bias)
__global__ __launch_bounds__(256) void gemm_kernel(
    const float* __restrict__ A, long aStride,
    const float* __restrict__ W,
    const float* __restrict__ bias,
    const float* __restrict__ res,
    const float* __restrict__ gate,
    float* __restrict__ C, long cStride,
    int M, int N, int K, int epi)
{
    __shared__ float As[8][128];
    __shared__ float Ws[8][128];
    A += (size_t)blockIdx.z * aStride;
    C += (size_t)blockIdx.z * cStride;
    int tid = threadIdx.x;
    int ty = tid >> 4, tx = tid & 15;
    int rowBase = blockIdx.y << 7;
    int colBase = blockIdx.x << 7;

    float acc[8][8];
#pragma unroll
    for (int i = 0; i < 8; i++)
#pragma unroll
        for (int j = 0; j < 8; j++) acc[i][j] = 0.f;

    for (int k0 = 0; k0 < K; k0 += 8) {
#pragma unroll
        for (int t = 0; t < 4; t++) {
            int idx = tid + t * 256;
            int r = idx >> 3, kk = idx & 7;
            As[kk][r] = A[(size_t)(rowBase + r) * K + k0 + kk];
        }
#pragma unroll
        for (int t = 0; t < 4; t++) {
            int idx = tid + t * 256;
            int kk = idx >> 7, c = idx & 127;
            Ws[kk][c] = W[(size_t)(k0 + kk) * N + colBase + c];
        }
        __syncthreads();
#pragma unroll
        for (int kk = 0; kk < 8; kk++) {
            float4 a0 = *(const float4*)&As[kk][ty * 8];
            float4 a1 = *(const float4*)&As[kk][ty * 8 + 4];
            float4 w0 = *(const float4*)&Ws[kk][tx * 8];
            float4 w1 = *(const float4*)&Ws[kk][tx * 8 + 4];
            float a[8] = {a0.x, a0.y, a0.z, a0.w, a1.x, a1.y, a1.z, a1.w};
            float w[8] = {w0.x, w0.y, w0.z, w0.w, w1.x, w1.y, w1.z, w1.w};
#pragma unroll
            for (int i = 0; i < 8; i++)
#pragma unroll
                for (int j = 0; j < 8; j++)
                    acc[i][j] = fmaf(a[i], w[j], acc[i][j]);
        }
        __syncthreads();
    }

    float gv = 0.f;
    if (epi == 1 || epi == 3) gv = tanhf(*gate);
#pragma unroll
    for (int i = 0; i < 8; i++) {
        int row = rowBase + ty * 8 + i;
#pragma unroll
        for (int j = 0; j < 8; j++) {
            int col = colBase + tx * 8 + j;
            size_t o = (size_t)row * N + col;
            float xv = acc[i][j];
            if (epi == 0)      xv += bias[col];
            else if (epi == 1) xv = res[o] + gv * (xv + bias[col]);
            else if (epi == 2) xv = 0.5f * xv * (1.f + erff(xv * 0.70710678118654752f));
            else               xv = res[o] + gv * xv;
            C[o] = xv;
        }
    }
}

// ---------------- Flash attention ----------------
// Br=64 queries/block, Bc=64 keys/tile, HD=128, 256 threads (16x16).
// Thread (ty,tx): S micro 4x4 (rows ty*4+i, cols tx*4+j), O micro 4x8 (cols tx*8+j).
#define KS_STRIDE 132
__global__ __launch_bounds__(256) void attn_kernel(
    const float* __restrict__ Q, const float* __restrict__ Kb, const float* __restrict__ Vb,
    const float* __restrict__ qmask, const float* __restrict__ pmask,
    const float* __restrict__ smask, const float* __restrict__ mmask,
    float* __restrict__ O)
{
    extern __shared__ float sh[];
    float* Qs   = sh;                     // 64*128
    float* Ks   = Qs + 64 * 128;          // 64*132 (padded, 16B-aligned rows)
    float* Vs   = Ks + 64 * KS_STRIDE;    // 64*128
    float* Ps   = Vs + 64 * 128;          // 64*64
    float* kmsk = Ps + 64 * 64;           // 64

    int b = blockIdx.z, h = blockIdx.y, q0 = blockIdx.x * 64;
    int tid = threadIdx.x;
    int ty = tid >> 4, tx = tid & 15;

    // Q tile, pre-scaled by H^-0.5 = 0.25
    for (int idx = tid; idx < 64 * 128; idx += 256) {
        int r = idx >> 7, c = idx & 127;
        Qs[idx] = Q[(size_t)(b * SQL + q0 + r) * DIM + h * HD + c] * 0.25f;
    }
    float qmr[4];
#pragma unroll
    for (int i = 0; i < 4; i++) qmr[i] = qmask[b * SQL + q0 + ty * 4 + i];

    float m[4], l[4], o[4][8];
#pragma unroll
    for (int i = 0; i < 4; i++) {
        m[i] = -1e30f; l[i] = 0.f;
#pragma unroll
        for (int j = 0; j < 8; j++) o[i][j] = 0.f;
    }

    for (int kt = 0; kt < SKV; kt += 64) {
        __syncthreads();   // prior-iter reads done before overwrite
        for (int idx = tid; idx < 64 * 128; idx += 256) {
            int r = idx >> 7, c = idx & 127;
            size_t g = (size_t)(b * SKV + kt + r) * DIM + h * HD + c;
            Ks[r * KS_STRIDE + c] = Kb[g];
            Vs[r * 128 + c]       = Vb[g];
        }
        if (tid < 64) {
            int kidx = kt + tid;
            float mv;
            if (kidx < SP)           mv = pmask[b * SP + kidx];
            else if (kidx < SP + SS) mv = smask[b * SS + kidx - SP];
            else                     mv = mmask[b * SMm + kidx - SP - SS];
            kmsk[tid] = mv;
        }
        __syncthreads();

        float s[4][4];
#pragma unroll
        for (int i = 0; i < 4; i++)
#pragma unroll
            for (int j = 0; j < 4; j++) s[i][j] = 0.f;

        for (int kk = 0; kk < 128; kk += 4) {
            float4 qv[4], kv[4];
#pragma unroll
            for (int i = 0; i < 4; i++) qv[i] = *(const float4*)&Qs[(ty * 4 + i) * 128 + kk];
#pragma unroll
            for (int j = 0; j < 4; j++) kv[j] = *(const float4*)&Ks[(tx * 4 + j) * KS_STRIDE + kk];
#pragma unroll
            for (int i = 0; i < 4; i++)
#pragma unroll
                for (int j = 0; j < 4; j++)
                    s[i][j] += qv[i].x * kv[j].x + qv[i].y * kv[j].y
                             + qv[i].z * kv[j].z + qv[i].w * kv[j].w;
        }
        // mask (qm * kvm == 0 -> -inf-ish); max is shift-invariant so online form matches ref
#pragma unroll
        for (int i = 0; i < 4; i++)
#pragma unroll
            for (int j = 0; j < 4; j++)
                if (qmr[i] == 0.f || kmsk[tx * 4 + j] == 0.f) s[i][j] = -1e30f;

#pragma unroll
        for (int i = 0; i < 4; i++) {
            float mt = fmaxf(fmaxf(s[i][0], s[i][1]), fmaxf(s[i][2], s[i][3]));
#pragma unroll
            for (int d = 1; d < 16; d <<= 1) mt = fmaxf(mt, __shfl_xor_sync(0xffffffffu, mt, d));
            float newm = fmaxf(m[i], mt);
            float alpha = __expf(m[i] - newm);
            float ps = 0.f;
#pragma unroll
            for (int j = 0; j < 4; j++) { float p = __expf(s[i][j] - newm); s[i][j] = p; ps += p; }
#pragma unroll
            for (int d = 1; d < 16; d <<= 1) ps += __shfl_xor_sync(0xffffffffu, ps, d);
            l[i] = l[i] * alpha + ps;
            m[i] = newm;
#pragma unroll
            for (int j = 0; j < 8; j++) o[i][j] *= alpha;
#pragma unroll
            for (int j = 0; j < 4; j++) Ps[(ty * 4 + i) * 64 + tx * 4 + j] = s[i][j];
        }
        __syncthreads();

        for (int kk = 0; kk < 64; kk++) {
            float4 v0 = *(const float4*)&Vs[kk * 128 + tx * 8];
            float4 v1 = *(const float4*)&Vs[kk * 128 + tx * 8 + 4];
#pragma unroll
            for (int i = 0; i < 4; i++) {
                float p = Ps[(ty * 4 + i) * 64 + kk];
                o[i][0] += p * v0.x; o[i][1] += p * v0.y;
                o[i][2] += p * v0.z; o[i][3] += p * v0.w;
                o[i][4] += p * v1.x; o[i][5] += p * v1.y;
                o[i][6] += p * v1.z; o[i][7] += p * v1.w;
            }
        }
    }

#pragma unroll
    for (int i = 0; i < 4; i++) {
        float inv = 1.f / l[i];
        size_t row = (size_t)(b * SQL + q0 + ty * 4 + i);
#pragma unroll
        for (int j = 0; j < 8; j++)
            O[row * DIM + h * HD + tx * 8 + j] = o[i][j] * inv;
    }
}

// ---------------- launch ----------------
extern "C" void kernel_launch(void* const* d_in, const int* in_sizes, int n_in,
                              void* d_out, int out_size)
{
    const float* x   = (const float*)d_in[0];
    const float* pkv = (const float*)d_in[1];
    const float* skv = (const float*)d_in[2];
    const float* mkv = (const float*)d_in[3];
    const float* qm  = (const float*)d_in[4];
    const float* pm  = (const float*)d_in[5];
    const float* smk = (const float*)d_in[6];
    const float* mmk = (const float*)d_in[7];
    const float* rw  = (const float*)d_in[8];
    const float* Wq  = (const float*)d_in[9];
    const float* bq  = (const float*)d_in[10];
    const float* Wkp = (const float*)d_in[11];
    const float* bkp = (const float*)d_in[12];
    const float* Wvp = (const float*)d_in[13];
    const float* bvp = (const float*)d_in[14];
    const float* Wks = (const float*)d_in[15];
    const float* bks = (const float*)d_in[16];
    const float* Wvs = (const float*)d_in[17];
    const float* bvs = (const float*)d_in[18];
    const float* Wkm = (const float*)d_in[19];
    const float* bkm = (const float*)d_in[20];
    const float* Wvm = (const float*)d_in[21];
    const float* bvm = (const float*)d_in[22];
    const float* Wo  = (const float*)d_in[23];
    const float* bo  = (const float*)d_in[24];
    const float* lg  = (const float*)d_in[25];
    const float* lb  = (const float*)d_in[26];
    const float* W1  = (const float*)d_in[27];
    const float* W2  = (const float*)d_in[28];
    const float* ga  = (const float*)d_in[29];
    const float* gf  = (const float*)d_in[30];
    float* out = (float*)d_out;

    float *xn, *q, *k, *v, *ctx, *hb, *ln, *mid;
    cudaGetSymbolAddress((void**)&xn,  g_xn);
    cudaGetSymbolAddress((void**)&q,   g_q);
    cudaGetSymbolAddress((void**)&k,   g_k);
    cudaGetSymbolAddress((void**)&v,   g_v);
    cudaGetSymbolAddress((void**)&ctx, g_ctx);
    cudaGetSymbolAddress((void**)&hb,  g_h);
    cudaGetSymbolAddress((void**)&ln,  g_ln);
    cudaGetSymbolAddress((void**)&mid, g_mid);

    dim3 blk(256);

    // 1) RMSNorm
    rms_kernel<<<BN * SQL, 256>>>(x, rw, xn);

    // 2) Q projection (batch folded: 2048 rows)
    gemm_kernel<<<dim3(DIM / 128, 16, 1), blk>>>(xn, 0, Wq, bq, nullptr, nullptr,
                                                 q, 0, BN * SQL, DIM, DIM, 0);

    // 3) K projections (per-segment, batched over z)
    gemm_kernel<<<dim3(DIM / 128, SP / 128, BN), blk>>>(pkv, (long)SP * DP, Wkp, bkp, nullptr, nullptr,
                                                        k, (long)SKV * DIM, SP, DIM, DP, 0);
    gemm_kernel<<<dim3(DIM / 128, SS / 128, BN), blk>>>(skv, (long)SS * DS, Wks, bks, nullptr, nullptr,
                                                        k + (size_t)SP * DIM, (long)SKV * DIM, SS, DIM, DS, 0);
    gemm_kernel<<<dim3(DIM / 128, SMm / 128, BN), blk>>>(mkv, (long)SMm * DMm, Wkm, bkm, nullptr, nullptr,
                                                         k + (size_t)(SP + SS) * DIM, (long)SKV * DIM, SMm, DIM, DMm, 0);
    // 4) V projections
    gemm_kernel<<<dim3(DIM / 128, SP / 128, BN), blk>>>(pkv, (long)SP * DP, Wvp, bvp, nullptr, nullptr,
                                                        v, (long)SKV * DIM, SP, DIM, DP, 0);
    gemm_kernel<<<dim3(DIM / 128, SS / 128, BN), blk>>>(skv, (long)SS * DS, Wvs, bvs, nullptr, nullptr,
                                                        v + (size_t)SP * DIM, (long)SKV * DIM, SS, DIM, DS, 0);
    gemm_kernel<<<dim3(DIM / 128, SMm / 128, BN), blk>>>(mkv, (long)SMm * DMm, Wvm, bvm, nullptr, nullptr,
                                                         v + (size_t)(SP + SS) * DIM, (long)SKV * DIM, SMm, DIM, DMm, 0);

    // 5) Flash attention
    size_t shmem = (size_t)(64 * 128 + 64 * KS_STRIDE + 64 * 128 + 64 * 64 + 64) * sizeof(float);
    cudaFuncSetAttribute(attn_kernel, cudaFuncAttributeMaxDynamicSharedMemorySize, (int)shmem);
    attn_kernel<<<dim3(SQL / 64, NH, BN), 256, shmem>>>(q, k, v, qm, pm, smk, mmk, ctx);

    // 6) Output projection + gated residual: h = x + tanh(ga)*(ctx@Wo + bo)
    gemm_kernel<<<dim3(DIM / 128, 16, 1), blk>>>(ctx, 0, Wo, bo, x, ga,
                                                 hb, 0, BN * SQL, DIM, DIM, 1);

    // 7) LayerNorm
    ln_kernel<<<BN * SQL, 256>>>(hb, lg, lb, ln);

    // 8) FFW up + exact GELU
    gemm_kernel<<<dim3(INNER / 128, 16, 1), blk>>>(ln, 0, W1, nullptr, nullptr, nullptr,
                                                   mid, 0, BN * SQL, INNER, DIM, 2);

    // 9) FFW down + gated residual -> final output
    gemm_kernel<<<dim3(DIM / 128, 16, 1), blk>>>(mid, 0, W2, nullptr, hb, gf,
                                                 out, 0, BN * SQL, DIM, INNER, 3);
}

// round 3
// speedup vs baseline: 1.7132x; 1.7132x over previous
#include <cuda_runtime.h>
#include <cuda_bf16.h>
#include <math.h>
#include <stdint.h>

// ---------------- problem constants ----------------
#define BN    2
#define SQL   1024
#define DIM   2048
#define NH    16
#define HD    128
#define SP    1024
#define SS    1024
#define SMm   512
#define SKV   2560
#define DP    1280
#define DS    1024
#define DMm   768
#define INNER 8192

typedef __nv_bfloat16 bf16;

// ---------------- scratch ----------------
__device__ __align__(256) float g_q  [BN*SQL*DIM];
__device__ __align__(256) float g_k  [BN*SKV*DIM];
__device__ __align__(256) float g_v  [BN*SKV*DIM];
__device__ __align__(256) float g_ctx[BN*SQL*DIM];
__device__ __align__(256) float g_h  [BN*SQL*DIM];

// activation splits
__device__ __align__(256) bf16 g_xnh [BN*SQL*DIM];
__device__ __align__(256) bf16 g_xnl [BN*SQL*DIM];
__device__ __align__(256) bf16 g_pkh [BN*SP*DP];
__device__ __align__(256) bf16 g_pkl [BN*SP*DP];
__device__ __align__(256) bf16 g_skh [BN*SS*DS];
__device__ __align__(256) bf16 g_skl [BN*SS*DS];
__device__ __align__(256) bf16 g_mkh [BN*SMm*DMm];
__device__ __align__(256) bf16 g_mkl [BN*SMm*DMm];
__device__ __align__(256) bf16 g_cth [BN*SQL*DIM];
__device__ __align__(256) bf16 g_ctl [BN*SQL*DIM];
__device__ __align__(256) bf16 g_lnh [BN*SQL*DIM];
__device__ __align__(256) bf16 g_lnl [BN*SQL*DIM];
__device__ __align__(256) bf16 g_mdh [BN*SQL*INNER];
__device__ __align__(256) bf16 g_mdl [BN*SQL*INNER];

// transposed weight splits ([N][K] K-major)
__device__ __align__(256) bf16 g_wqh [DIM*DIM];
__device__ __align__(256) bf16 g_wql [DIM*DIM];
__device__ __align__(256) bf16 g_kph [DIM*DP];
__device__ __align__(256) bf16 g_kpl [DIM*DP];
__device__ __align__(256) bf16 g_vph [DIM*DP];
__device__ __align__(256) bf16 g_vpl [DIM*DP];
__device__ __align__(256) bf16 g_ksh [DIM*DS];
__device__ __align__(256) bf16 g_ksl [DIM*DS];
__device__ __align__(256) bf16 g_vsh [DIM*DS];
__device__ __align__(256) bf16 g_vsl [DIM*DS];
__device__ __align__(256) bf16 g_kmh [DIM*DMm];
__device__ __align__(256) bf16 g_kml [DIM*DMm];
__device__ __align__(256) bf16 g_vmh [DIM*DMm];
__device__ __align__(256) bf16 g_vml [DIM*DMm];
__device__ __align__(256) bf16 g_woh [DIM*DIM];
__device__ __align__(256) bf16 g_wol [DIM*DIM];
__device__ __align__(256) bf16 g_w1h [INNER*DIM];
__device__ __align__(256) bf16 g_w1l [INNER*DIM];
__device__ __align__(256) bf16 g_w2h [DIM*INNER];
__device__ __align__(256) bf16 g_w2l [DIM*INNER];

// ---------------- helpers ----------------
#define CP16(dst, src) asm volatile("cp.async.cg.shared.global [%0], [%1], 16;" :: "r"(dst), "l"(src))
#define CP_COMMIT()  asm volatile("cp.async.commit_group;" ::: "memory")
#define CP_WAIT(n)   asm volatile("cp.async.wait_group %0;" :: "n"(n) : "memory")

__device__ __forceinline__ uint32_t smem_u32(const void* p) {
    uint32_t a;
    asm("{ .reg .u64 t; cvta.to.shared.u64 t, %1; cvt.u32.u64 %0, t; }" : "=r"(a) : "l"(p));
    return a;
}

__device__ __forceinline__ void mma_bf16(float* c, const uint32_t* a, const uint32_t* b) {
    asm volatile("mma.sync.aligned.m16n8k16.row.col.f32.bf16.bf16.f32 "
        "{%0,%1,%2,%3}, {%4,%5,%6,%7}, {%8,%9}, {%0,%1,%2,%3};"
        : "+f"(c[0]), "+f"(c[1]), "+f"(c[2]), "+f"(c[3])
        : "r"(a[0]), "r"(a[1]), "r"(a[2]), "r"(a[3]), "r"(b[0]), "r"(b[1]));
}

__device__ __forceinline__ void split2(float v, bf16& h, bf16& l) {
    h = __float2bfloat16(v);
    l = __float2bfloat16(v - __bfloat162float(h));
}

// ---------------- split kernels ----------------
__global__ __launch_bounds__(256) void split_kernel(const float* __restrict__ x,
                                                    bf16* __restrict__ hi, bf16* __restrict__ lo, int n) {
    int i = blockIdx.x * 256 + threadIdx.x;
    if (i < n) { bf16 h, l; split2(x[i], h, l); hi[i] = h; lo[i] = l; }
}

// transpose + split: W[K][N] -> hi/lo [N][K]
__global__ __launch_bounds__(256) void tsplit_kernel(const float* __restrict__ W,
                                                     bf16* __restrict__ hi, bf16* __restrict__ lo,
                                                     int K, int N) {
    __shared__ float t[32][33];
    int n0 = blockIdx.x * 32, k0 = blockIdx.y * 32;
    int tx = threadIdx.x & 31, ty = threadIdx.x >> 5;
#pragma unroll
    for (int r = 0; r < 32; r += 8)
        t[ty + r][tx] = W[(size_t)(k0 + ty + r) * N + n0 + tx];
    __syncthreads();
#pragma unroll
    for (int r = 0; r < 32; r += 8) {
        float v = t[tx][ty + r];
        bf16 h, l; split2(v, h, l);
        size_t o = (size_t)(n0 + ty + r) * K + k0 + tx;
        hi[o] = h; lo[o] = l;
    }
}

__global__ __launch_bounds__(256) void rms_split_kernel(
    const float* __restrict__ x, const float* __restrict__ w,
    bf16* __restrict__ yh, bf16* __restrict__ yl) {
    __shared__ float red[256];
    int row = blockIdx.x;
    const float* xr = x + (size_t)row * DIM;
    float ss = 0.f;
    for (int c = threadIdx.x; c < DIM; c += 256) { float v = xr[c]; ss += v * v; }
    red[threadIdx.x] = ss; __syncthreads();
    for (int s = 128; s > 0; s >>= 1) {
        if (threadIdx.x < s) red[threadIdx.x] += red[threadIdx.x + s];
        __syncthreads();
    }
    float inv = rsqrtf(red[0] / (float)DIM + 1e-6f);
    for (int c = threadIdx.x; c < DIM; c += 256) {
        bf16 h, l; split2(xr[c] * inv * w[c], h, l);
        size_t o = (size_t)row * DIM + c;
        yh[o] = h; yl[o] = l;
    }
}

__global__ __launch_bounds__(256) void ln_split_kernel(
    const float* __restrict__ x, const float* __restrict__ g, const float* __restrict__ b,
    bf16* __restrict__ yh, bf16* __restrict__ yl) {
    __shared__ float r1[256], r2[256];
    int row = blockIdx.x;
    const float* xr = x + (size_t)row * DIM;
    float s1 = 0.f, s2 = 0.f;
    for (int c = threadIdx.x; c < DIM; c += 256) { float v = xr[c]; s1 += v; s2 += v * v; }
    r1[threadIdx.x] = s1; r2[threadIdx.x] = s2; __syncthreads();
    for (int s = 128; s > 0; s >>= 1) {
        if (threadIdx.x < s) { r1[threadIdx.x] += r1[threadIdx.x + s]; r2[threadIdx.x] += r2[threadIdx.x + s]; }
        __syncthreads();
    }
    float mu = r1[0] / (float)DIM;
    float rstd = rsqrtf(r2[0] / (float)DIM - mu * mu + 1e-5f);
    for (int c = threadIdx.x; c < DIM; c += 256) {
        bf16 h, l; split2((xr[c] - mu) * rstd * g[c] + b[c], h, l);
        size_t o = (size_t)row * DIM + c;
        yh[o] = h; yl[o] = l;
    }
}

// ---------------- mma.sync bf16x3 GEMM ----------------
// C[M,N] = A[M,K] @ B^T ; B stored [N][K] K-major. Acc = Ahi*Bhi + Ahi*Blo + Alo*Bhi.
// Block tile 128x128, Ktile=32, 8 warps (4m x 2n), warp tile 32x64.
// smem stage: 4 arrays (Ahi,Alo,Bhi,Blo), each 128 rows x 40 bf16 (80B) = 10240B -> 40960B/stage, x2 stages.
// epi: 0: C=acc+bias | 1: C=res+tanh(g)*(acc+bias) | 2: gelu(acc)->split bf16 | 3: C=res+tanh(g)*acc
#define RS    40          // smem row stride in bf16 elems
#define ARRB  10240       // bytes per array per stage
#define STGB  40960       // bytes per stage

__global__ __launch_bounds__(256) void gemm_mma(
    const bf16* __restrict__ Ahi, const bf16* __restrict__ Alo, long aStride,
    const bf16* __restrict__ Bhi, const bf16* __restrict__ Blo,
    const float* __restrict__ bias, const float* __restrict__ res, const float* __restrict__ gate,
    float* __restrict__ C, bf16* __restrict__ Chi, bf16* __restrict__ Clo,
    long cStride, int M, int N, int K, int epi)
{
    extern __shared__ __align__(128) char dsm[];
    bf16* sm = (bf16*)dsm;

    int tid = threadIdx.x, wid = tid >> 5, lid = tid & 31;
    int wm = wid & 3, wn = wid >> 2;          // 4 x 2 warp grid
    int m0 = blockIdx.y << 7, n0 = blockIdx.x << 7;

    Ahi += (size_t)blockIdx.z * aStride;
    Alo += (size_t)blockIdx.z * aStride;
    C   += (size_t)blockIdx.z * cStride;
    if (Chi) { Chi += (size_t)blockIdx.z * cStride; Clo += (size_t)blockIdx.z * cStride; }

    uint32_t sbase = smem_u32(dsm);
    const bf16* aptr[4] = { Ahi + (size_t)m0 * K, Alo + (size_t)m0 * K,
                            Bhi + (size_t)n0 * K, Blo + (size_t)n0 * K };

    // stage loader: 2048 cp.async of 16B over 256 threads = 8 each
    auto load_stage = [&](int k0, int st) {
        uint32_t base = sbase + (uint32_t)st * STGB;
#pragma unroll
        for (int i = 0; i < 8; i++) {
            int idx = tid + i * 256;
            int arr = idx >> 9;            // /512
            int rem = idx & 511;
            int row = rem >> 2;
            int ch  = rem & 3;
            uint32_t d = base + (uint32_t)arr * ARRB + (uint32_t)(row * RS * 2 + ch * 16);
            CP16(d, aptr[arr] + (size_t)row * K + k0 + ch * 8);
        }
    };

    float c[2][8][4];
#pragma unroll
    for (int mi = 0; mi < 2; mi++)
#pragma unroll
        for (int ni = 0; ni < 8; ni++)
#pragma unroll
            for (int r = 0; r < 4; r++) c[mi][ni][r] = 0.f;

    const int nt = K >> 5;   // Ktile = 32
    load_stage(0, 0);
    CP_COMMIT();

    for (int t = 0; t < nt; t++) {
        int st = t & 1;
        if (t + 1 < nt) {
            load_stage((t + 1) << 5, st ^ 1);
            CP_COMMIT();
            CP_WAIT(1);
        } else {
            CP_WAIT(0);
        }
        __syncthreads();

        const bf16* As_h = sm + (st * STGB) / 2;
        const bf16* As_l = As_h + ARRB / 2;
        const bf16* Bs_h = As_h + 2 * (ARRB / 2);
        const bf16* Bs_l = As_h + 3 * (ARRB / 2);

#pragma unroll
        for (int ks = 0; ks < 2; ks++) {
            int ko = ks * 16;
            int arow = (lid >> 2);
            int acol = ko + (lid & 3) * 2;

            uint32_t ah[2][4], al[2][4];
#pragma unroll
            for (int mi = 0; mi < 2; mi++) {
                int r = wm * 32 + mi * 16 + arow;
                ah[mi][0] = *(const uint32_t*)(As_h + r * RS + acol);
                ah[mi][1] = *(const uint32_t*)(As_h + (r + 8) * RS + acol);
                ah[mi][2] = *(const uint32_t*)(As_h + r * RS + acol + 8);
                ah[mi][3] = *(const uint32_t*)(As_h + (r + 8) * RS + acol + 8);
                al[mi][0] = *(const uint32_t*)(As_l + r * RS + acol);
                al[mi][1] = *(const uint32_t*)(As_l + (r + 8) * RS + acol);
                al[mi][2] = *(const uint32_t*)(As_l + r * RS + acol + 8);
                al[mi][3] = *(const uint32_t*)(As_l + (r + 8) * RS + acol + 8);
            }
            // two halves of 4 n-tiles to limit register pressure
#pragma unroll
            for (int nh2 = 0; nh2 < 2; nh2++) {
                uint32_t bh[4][2], bl[4][2];
#pragma unroll
                for (int nj = 0; nj < 4; nj++) {
                    int ni = nh2 * 4 + nj;
                    int nr = wn * 64 + ni * 8 + (lid >> 2);
                    int kb = ko + (lid & 3) * 2;
                    bh[nj][0] = *(const uint32_t*)(Bs_h + nr * RS + kb);
                    bh[nj][1] = *(const uint32_t*)(Bs_h + nr * RS + kb + 8);
                    bl[nj][0] = *(const uint32_t*)(Bs_l + nr * RS + kb);
                    bl[nj][1] = *(const uint32_t*)(Bs_l + nr * RS + kb + 8);
                }
#pragma unroll
                for (int mi = 0; mi < 2; mi++)
#pragma unroll
                    for (int nj = 0; nj < 4; nj++) {
                        float* cc = c[mi][nh2 * 4 + nj];
                        mma_bf16(cc, ah[mi], bh[nj]);
                        mma_bf16(cc, ah[mi], bl[nj]);
                        mma_bf16(cc, al[mi], bh[nj]);
                    }
            }
        }
        __syncthreads();
    }

    // ---------------- epilogue ----------------
    float gv = (epi == 1 || epi == 3) ? tanhf(*gate) : 0.f;
#pragma unroll
    for (int mi = 0; mi < 2; mi++) {
#pragma unroll
        for (int ni = 0; ni < 8; ni++) {
            int col = n0 + wn * 64 + ni * 8 + (lid & 3) * 2;
            float bcol0 = 0.f, bcol1 = 0.f;
            if (epi == 0 || epi == 1) { bcol0 = bias[col]; bcol1 = bias[col + 1]; }
#pragma unroll
            for (int rh = 0; rh < 2; rh++) {
                int m = m0 + wm * 32 + mi * 16 + (lid >> 2) + rh * 8;
                size_t o = (size_t)m * N + col;
                float v0 = c[mi][ni][rh * 2 + 0];
                float v1 = c[mi][ni][rh * 2 + 1];
                if (epi == 0) {
                    C[o] = v0 + bcol0; C[o + 1] = v1 + bcol1;
                } else if (epi == 1) {
                    C[o]     = res[o]     + gv * (v0 + bcol0);
                    C[o + 1] = res[o + 1] + gv * (v1 + bcol1);
                } else if (epi == 2) {
                    float g0 = 0.5f * v0 * (1.f + erff(v0 * 0.70710678118654752f));
                    float g1 = 0.5f * v1 * (1.f + erff(v1 * 0.70710678118654752f));
                    bf16 h, l;
                    split2(g0, h, l); Chi[o] = h;     Clo[o] = l;
                    split2(g1, h, l); Chi[o + 1] = h; Clo[o + 1] = l;
                } else {
                    C[o]     = res[o]     + gv * v0;
                    C[o + 1] = res[o + 1] + gv * v1;
                }
            }
        }
    }
}

// ---------------- Flash attention (fp32) ----------------
#define KS_STRIDE 132
__global__ __launch_bounds__(256) void attn_kernel(
    const float* __restrict__ Q, const float* __restrict__ Kb, const float* __restrict__ Vb,
    const float* __restrict__ qmask, const float* __restrict__ pmask,
    const float* __restrict__ smask, const float* __restrict__ mmask,
    float* __restrict__ O)
{
    extern __shared__ float sh[];
    float* Qs   = sh;
    float* Ks   = Qs + 64 * 128;
    float* Vs   = Ks + 64 * KS_STRIDE;
    float* Ps   = Vs + 64 * 128;
    float* kmsk = Ps + 64 * 64;

    int b = blockIdx.z, h = blockIdx.y, q0 = blockIdx.x * 64;
    int tid = threadIdx.x;
    int ty = tid >> 4, tx = tid & 15;

    for (int idx = tid; idx < 64 * 128; idx += 256) {
        int r = idx >> 7, c = idx & 127;
        Qs[idx] = Q[(size_t)(b * SQL + q0 + r) * DIM + h * HD + c] * 0.25f;
    }
    float qmr[4];
#pragma unroll
    for (int i = 0; i < 4; i++) qmr[i] = qmask[b * SQL + q0 + ty * 4 + i];

    float m[4], l[4], o[4][8];
#pragma unroll
    for (int i = 0; i < 4; i++) {
        m[i] = -1e30f; l[i] = 0.f;
#pragma unroll
        for (int j = 0; j < 8; j++) o[i][j] = 0.f;
    }

    for (int kt = 0; kt < SKV; kt += 64) {
        __syncthreads();
        for (int idx = tid; idx < 64 * 128; idx += 256) {
            int r = idx >> 7, c = idx & 127;
            size_t g = (size_t)(b * SKV + kt + r) * DIM + h * HD + c;
            Ks[r * KS_STRIDE + c] = Kb[g];
            Vs[r * 128 + c]       = Vb[g];
        }
        if (tid < 64) {
            int kidx = kt + tid;
            float mv;
            if (kidx < SP)           mv = pmask[b * SP + kidx];
            else if (kidx < SP + SS) mv = smask[b * SS + kidx - SP];
            else                     mv = mmask[b * SMm + kidx - SP - SS];
            kmsk[tid] = mv;
        }
        __syncthreads();

        float s[4][4];
#pragma unroll
        for (int i = 0; i < 4; i++)
#pragma unroll
            for (int j = 0; j < 4; j++) s[i][j] = 0.f;

        for (int kk = 0; kk < 128; kk += 4) {
            float4 qv[4], kv[4];
#pragma unroll
            for (int i = 0; i < 4; i++) qv[i] = *(const float4*)&Qs[(ty * 4 + i) * 128 + kk];
#pragma unroll
            for (int j = 0; j < 4; j++) kv[j] = *(const float4*)&Ks[(tx * 4 + j) * KS_STRIDE + kk];
#pragma unroll
            for (int i = 0; i < 4; i++)
#pragma unroll
                for (int j = 0; j < 4; j++)
                    s[i][j] += qv[i].x * kv[j].x + qv[i].y * kv[j].y
                             + qv[i].z * kv[j].z + qv[i].w * kv[j].w;
        }
#pragma unroll
        for (int i = 0; i < 4; i++)
#pragma unroll
            for (int j = 0; j < 4; j++)
                if (qmr[i] == 0.f || kmsk[tx * 4 + j] == 0.f) s[i][j] = -1e30f;

#pragma unroll
        for (int i = 0; i < 4; i++) {
            float mt = fmaxf(fmaxf(s[i][0], s[i][1]), fmaxf(s[i][2], s[i][3]));
#pragma unroll
            for (int d = 1; d < 16; d <<= 1) mt = fmaxf(mt, __shfl_xor_sync(0xffffffffu, mt, d));
            float newm = fmaxf(m[i], mt);
            float alpha = __expf(m[i] - newm);
            float ps = 0.f;
#pragma unroll
            for (int j = 0; j < 4; j++) { float p = __expf(s[i][j] - newm); s[i][j] = p; ps += p; }
#pragma unroll
            for (int d = 1; d < 16; d <<= 1) ps += __shfl_xor_sync(0xffffffffu, ps, d);
            l[i] = l[i] * alpha + ps;
            m[i] = newm;
#pragma unroll
            for (int j = 0; j < 8; j++) o[i][j] *= alpha;
#pragma unroll
            for (int j = 0; j < 4; j++) Ps[(ty * 4 + i) * 64 + tx * 4 + j] = s[i][j];
        }
        __syncthreads();

        for (int kk = 0; kk < 64; kk++) {
            float4 v0 = *(const float4*)&Vs[kk * 128 + tx * 8];
            float4 v1 = *(const float4*)&Vs[kk * 128 + tx * 8 + 4];
#pragma unroll
            for (int i = 0; i < 4; i++) {
                float p = Ps[(ty * 4 + i) * 64 + kk];
                o[i][0] += p * v0.x; o[i][1] += p * v0.y;
                o[i][2] += p * v0.z; o[i][3] += p * v0.w;
                o[i][4] += p * v1.x; o[i][5] += p * v1.y;
                o[i][6] += p * v1.z; o[i][7] += p * v1.w;
            }
        }
    }

#pragma unroll
    for (int i = 0; i < 4; i++) {
        float inv = 1.f / l[i];
        size_t rowo = (size_t)(b * SQL + q0 + ty * 4 + i);
#pragma unroll
        for (int j = 0; j < 8; j++)
            O[rowo * DIM + h * HD + tx * 8 + j] = o[i][j] * inv;
    }
}

// ---------------- launch ----------------
extern "C" void kernel_launch(void* const* d_in, const int* in_sizes, int n_in,
                              void* d_out, int out_size)
{
    const float* x   = (const float*)d_in[0];
    const float* pkv = (const float*)d_in[1];
    const float* skv = (const float*)d_in[2];
    const float* mkv = (const float*)d_in[3];
    const float* qm  = (const float*)d_in[4];
    const float* pm  = (const float*)d_in[5];
    const float* smk = (const float*)d_in[6];
    const float* mmk = (const float*)d_in[7];
    const float* rw  = (const float*)d_in[8];
    const float* Wq  = (const float*)d_in[9];
    const float* bq  = (const float*)d_in[10];
    const float* Wkp = (const float*)d_in[11];
    const float* bkp = (const float*)d_in[12];
    const float* Wvp = (const float*)d_in[13];
    const float* bvp = (const float*)d_in[14];
    const float* Wks = (const float*)d_in[15];
    const float* bks = (const float*)d_in[16];
    const float* Wvs = (const float*)d_in[17];
    const float* bvs = (const float*)d_in[18];
    const float* Wkm = (const float*)d_in[19];
    const float* bkm = (const float*)d_in[20];
    const float* Wvm = (const float*)d_in[21];
    const float* bvm = (const float*)d_in[22];
    const float* Wo  = (const float*)d_in[23];
    const float* bo  = (const float*)d_in[24];
    const float* lg  = (const float*)d_in[25];
    const float* lb  = (const float*)d_in[26];
    const float* W1  = (const float*)d_in[27];
    const float* W2  = (const float*)d_in[28];
    const float* ga  = (const float*)d_in[29];
    const float* gf  = (const float*)d_in[30];
    float* out = (float*)d_out;

    float *q, *k, *v, *ctx, *hb;
    cudaGetSymbolAddress((void**)&q,   g_q);
    cudaGetSymbolAddress((void**)&k,   g_k);
    cudaGetSymbolAddress((void**)&v,   g_v);
    cudaGetSymbolAddress((void**)&ctx, g_ctx);
    cudaGetSymbolAddress((void**)&hb,  g_h);

    bf16 *xnh, *xnl, *pkh, *pkl, *skh, *skl, *mkh, *mkl, *cth, *ctl, *lnh, *lnl, *mdh, *mdl;
    cudaGetSymbolAddress((void**)&xnh, g_xnh); cudaGetSymbolAddress((void**)&xnl, g_xnl);
    cudaGetSymbolAddress((void**)&pkh, g_pkh); cudaGetSymbolAddress((void**)&pkl, g_pkl);
    cudaGetSymbolAddress((void**)&skh, g_skh); cudaGetSymbolAddress((void**)&skl, g_skl);
    cudaGetSymbolAddress((void**)&mkh, g_mkh); cudaGetSymbolAddress((void**)&mkl, g_mkl);
    cudaGetSymbolAddress((void**)&cth, g_cth); cudaGetSymbolAddress((void**)&ctl, g_ctl);
    cudaGetSymbolAddress((void**)&lnh, g_lnh); cudaGetSymbolAddress((void**)&lnl, g_lnl);
    cudaGetSymbolAddress((void**)&mdh, g_mdh); cudaGetSymbolAddress((void**)&mdl, g_mdl);

    bf16 *wqh, *wql, *kph, *kpl, *vph, *vpl, *ksh, *ksl, *vsh, *vsl, *kmh, *kml, *vmh, *vml, *woh, *wol, *w1h, *w1l, *w2h, *w2l;
    cudaGetSymbolAddress((void**)&wqh, g_wqh); cudaGetSymbolAddress((void**)&wql, g_wql);
    cudaGetSymbolAddress((void**)&kph, g_kph); cudaGetSymbolAddress((void**)&kpl, g_kpl);
    cudaGetSymbolAddress((void**)&vph, g_vph); cudaGetSymbolAddress((void**)&vpl, g_vpl);
    cudaGetSymbolAddress((void**)&ksh, g_ksh); cudaGetSymbolAddress((void**)&ksl, g_ksl);
    cudaGetSymbolAddress((void**)&vsh, g_vsh); cudaGetSymbolAddress((void**)&vsl, g_vsl);
    cudaGetSymbolAddress((void**)&kmh, g_kmh); cudaGetSymbolAddress((void**)&kml, g_kml);
    cudaGetSymbolAddress((void**)&vmh, g_vmh); cudaGetSymbolAddress((void**)&vml, g_vml);
    cudaGetSymbolAddress((void**)&woh, g_woh); cudaGetSymbolAddress((void**)&wol, g_wol);
    cudaGetSymbolAddress((void**)&w1h, g_w1h); cudaGetSymbolAddress((void**)&w1l, g_w1l);
    cudaGetSymbolAddress((void**)&w2h, g_w2h); cudaGetSymbolAddress((void**)&w2l, g_w2l);

    size_t gemm_sh = 2 * STGB;                 // 80 KB
    size_t shA = (size_t)(64 * 128 + 64 * KS_STRIDE + 64 * 128 + 64 * 64 + 64) * sizeof(float);
    cudaFuncSetAttribute(gemm_mma, cudaFuncAttributeMaxDynamicSharedMemorySize, (int)gemm_sh);
    cudaFuncSetAttribute(attn_kernel, cudaFuncAttributeMaxDynamicSharedMemorySize, (int)shA);

    // 1) weight transpose + split
    tsplit_kernel<<<dim3(DIM / 32, DIM / 32),  256>>>(Wq,  wqh, wql, DIM,   DIM);
    tsplit_kernel<<<dim3(DIM / 32, DP / 32),   256>>>(Wkp, kph, kpl, DP,    DIM);
    tsplit_kernel<<<dim3(DIM / 32, DP / 32),   256>>>(Wvp, vph, vpl, DP,    DIM);
    tsplit_kernel<<<dim3(DIM / 32, DS / 32),   256>>>(Wks, ksh, ksl, DS,    DIM);
    tsplit_kernel<<<dim3(DIM / 32, DS / 32),   256>>>(Wvs, vsh, vsl, DS,    DIM);
    tsplit_kernel<<<dim3(DIM / 32, DMm / 32),  256>>>(Wkm, kmh, kml, DMm,   DIM);
    tsplit_kernel<<<dim3(DIM / 32, DMm / 32),  256>>>(Wvm, vmh, vml, DMm,   DIM);
    tsplit_kernel<<<dim3(DIM / 32, DIM / 32),  256>>>(Wo,  woh, wol, DIM,   DIM);
    tsplit_kernel<<<dim3(INNER / 32, DIM / 32), 256>>>(W1, w1h, w1l, DIM,   INNER);
    tsplit_kernel<<<dim3(DIM / 32, INNER / 32), 256>>>(W2, w2h, w2l, INNER, DIM);

    // 2) activation splits
    rms_split_kernel<<<BN * SQL, 256>>>(x, rw, xnh, xnl);
    split_kernel<<<(BN * SP * DP) / 256,   256>>>(pkv, pkh, pkl, BN * SP * DP);
    split_kernel<<<(BN * SS * DS) / 256,   256>>>(skv, skh, skl, BN * SS * DS);
    split_kernel<<<(BN * SMm * DMm) / 256, 256>>>(mkv, mkh, mkl, BN * SMm * DMm);

    // 3) projections (tensor cores)
    gemm_mma<<<dim3(DIM / 128, 16, 1), 256, gemm_sh>>>(xnh, xnl, 0, wqh, wql, bq, nullptr, nullptr,
                                                       q, nullptr, nullptr, 0, BN * SQL, DIM, DIM, 0);
    gemm_mma<<<dim3(DIM / 128, SP / 128, BN), 256, gemm_sh>>>(pkh, pkl, (long)SP * DP, kph, kpl, bkp, nullptr, nullptr,
                                                              k, nullptr, nullptr, (long)SKV * DIM, SP, DIM, DP, 0);
    gemm_mma<<<dim3(DIM / 128, SS / 128, BN), 256, gemm_sh>>>(skh, skl, (long)SS * DS, ksh, ksl, bks, nullptr, nullptr,
                                                              k + (size_t)SP * DIM, nullptr, nullptr, (long)SKV * DIM, SS, DIM, DS, 0);
    gemm_mma<<<dim3(DIM / 128, SMm / 128, BN), 256, gemm_sh>>>(mkh, mkl, (long)SMm * DMm, kmh, kml, bkm, nullptr, nullptr,
                                                               k + (size_t)(SP + SS) * DIM, nullptr, nullptr, (long)SKV * DIM, SMm, DIM, DMm, 0);
    gemm_mma<<<dim3(DIM / 128, SP / 128, BN), 256, gemm_sh>>>(pkh, pkl, (long)SP * DP, vph, vpl, bvp, nullptr, nullptr,
                                                              v, nullptr, nullptr, (long)SKV * DIM, SP, DIM, DP, 0);
    gemm_mma<<<dim3(DIM / 128, SS / 128, BN), 256, gemm_sh>>>(skh, skl, (long)SS * DS, vsh, vsl, bvs, nullptr, nullptr,
                                                              v + (size_t)SP * DIM, nullptr, nullptr, (long)SKV * DIM, SS, DIM, DS, 0);
    gemm_mma<<<dim3(DIM / 128, SMm / 128, BN), 256, gemm_sh>>>(mkh, mkl, (long)SMm * DMm, vmh, vml, bvm, nullptr, nullptr,
                                                               v + (size_t)(SP + SS) * DIM, nullptr, nullptr, (long)SKV * DIM, SMm, DIM, DMm, 0);

    // 4) attention (fp32)
    attn_kernel<<<dim3(SQL / 64, NH, BN), 256, shA>>>(q, k, v, qm, pm, smk, mmk, ctx);

    // 5) split ctx; Wo projection + gated residual
    split_kernel<<<(BN * SQL * DIM) / 256, 256>>>(ctx, cth, ctl, BN * SQL * DIM);
    gemm_mma<<<dim3(DIM / 128, 16, 1), 256, gemm_sh>>>(cth, ctl, 0, woh, wol, bo, x, ga,
                                                       hb, nullptr, nullptr, 0, BN * SQL, DIM, DIM, 1);

    // 6) LayerNorm -> split
    ln_split_kernel<<<BN * SQL, 256>>>(hb, lg, lb, lnh, lnl);

    // 7) FFW up + GELU -> split
    gemm_mma<<<dim3(INNER / 128, 16, 1), 256, gemm_sh>>>(lnh, lnl, 0, w1h, w1l, nullptr, nullptr, nullptr,
                                                         nullptr, mdh, mdl, 0, BN * SQL, INNER, DIM, 2);

    // 8) FFW down + gated residual -> out
    gemm_mma<<<dim3(DIM / 128, 16, 1), 256, gemm_sh>>>(mdh, mdl, 0, w2h, w2l, nullptr, hb, gf,
                                                       out, nullptr, nullptr, 0, BN * SQL, DIM, INNER, 3);
}

// round 4
// speedup vs baseline: 3.4823x; 2.0326x over previous
#include <cuda_runtime.h>
#include <cuda_bf16.h>
#include <math.h>
#include <stdint.h>

// ---------------- problem constants ----------------
#define BN    2
#define SQL   1024
#define DIM   2048
#define NH    16
#define HD    128
#define SP    1024
#define SS    1024
#define SMm   512
#define SKV   2560
#define DP    1280
#define DS    1024
#define DMm   768
#define INNER 8192

typedef __nv_bfloat16 bf16;

// ---------------- scratch ----------------
__device__ __align__(256) float g_h  [BN*SQL*DIM];

// activation splits
__device__ __align__(256) bf16 g_xnh [BN*SQL*DIM];
__device__ __align__(256) bf16 g_xnl [BN*SQL*DIM];
__device__ __align__(256) bf16 g_pkh [BN*SP*DP];
__device__ __align__(256) bf16 g_pkl [BN*SP*DP];
__device__ __align__(256) bf16 g_skh [BN*SS*DS];
__device__ __align__(256) bf16 g_skl [BN*SS*DS];
__device__ __align__(256) bf16 g_mkh [BN*SMm*DMm];
__device__ __align__(256) bf16 g_mkl [BN*SMm*DMm];
__device__ __align__(256) bf16 g_cth [BN*SQL*DIM];
__device__ __align__(256) bf16 g_ctl [BN*SQL*DIM];
__device__ __align__(256) bf16 g_lnh [BN*SQL*DIM];
__device__ __align__(256) bf16 g_lnl [BN*SQL*DIM];
__device__ __align__(256) bf16 g_mdh [BN*SQL*INNER];
__device__ __align__(256) bf16 g_mdl [BN*SQL*INNER];

// q/k/v bf16 splits (q pre-scaled), v transposed [D][SKV]
__device__ __align__(256) bf16 g_qh  [BN*SQL*DIM];
__device__ __align__(256) bf16 g_ql  [BN*SQL*DIM];
__device__ __align__(256) bf16 g_kh2 [BN*SKV*DIM];
__device__ __align__(256) bf16 g_kl2 [BN*SKV*DIM];
__device__ __align__(256) bf16 g_vth [BN*DIM*SKV];
__device__ __align__(256) bf16 g_vtl [BN*DIM*SKV];

// transposed weight splits ([N][K] K-major)
__device__ __align__(256) bf16 g_wqh [DIM*DIM];
__device__ __align__(256) bf16 g_wql [DIM*DIM];
__device__ __align__(256) bf16 g_kph [DIM*DP];
__device__ __align__(256) bf16 g_kpl [DIM*DP];
__device__ __align__(256) bf16 g_vph [DIM*DP];
__device__ __align__(256) bf16 g_vpl [DIM*DP];
__device__ __align__(256) bf16 g_ksh [DIM*DS];
__device__ __align__(256) bf16 g_ksl [DIM*DS];
__device__ __align__(256) bf16 g_vsh [DIM*DS];
__device__ __align__(256) bf16 g_vsl [DIM*DS];
__device__ __align__(256) bf16 g_kmh [DIM*DMm];
__device__ __align__(256) bf16 g_kml [DIM*DMm];
__device__ __align__(256) bf16 g_vmh [DIM*DMm];
__device__ __align__(256) bf16 g_vml [DIM*DMm];
__device__ __align__(256) bf16 g_woh [DIM*DIM];
__device__ __align__(256) bf16 g_wol [DIM*DIM];
__device__ __align__(256) bf16 g_w1h [INNER*DIM];
__device__ __align__(256) bf16 g_w1l [INNER*DIM];
__device__ __align__(256) bf16 g_w2h [DIM*INNER];
__device__ __align__(256) bf16 g_w2l [DIM*INNER];

// ---------------- helpers ----------------
#define CP16(dst, src) asm volatile("cp.async.cg.shared.global [%0], [%1], 16;" :: "r"(dst), "l"(src))
#define CP4(dst, src)  asm volatile("cp.async.ca.shared.global [%0], [%1], 4;"  :: "r"(dst), "l"(src))
#define CP_COMMIT()  asm volatile("cp.async.commit_group;" ::: "memory")
#define CP_WAIT(n)   asm volatile("cp.async.wait_group %0;" :: "n"(n) : "memory")

__device__ __forceinline__ uint32_t smem_u32(const void* p) {
    uint32_t a;
    asm("{ .reg .u64 t; cvta.to.shared.u64 t, %1; cvt.u32.u64 %0, t; }" : "=r"(a) : "l"(p));
    return a;
}
__device__ __forceinline__ void mma_bf16(float* c, const uint32_t* a, const uint32_t* b) {
    asm volatile("mma.sync.aligned.m16n8k16.row.col.f32.bf16.bf16.f32 "
        "{%0,%1,%2,%3}, {%4,%5,%6,%7}, {%8,%9}, {%0,%1,%2,%3};"
        : "+f"(c[0]), "+f"(c[1]), "+f"(c[2]), "+f"(c[3])
        : "r"(a[0]), "r"(a[1]), "r"(a[2]), "r"(a[3]), "r"(b[0]), "r"(b[1]));
}
__device__ __forceinline__ void ldmx4(uint32_t* r, uint32_t addr) {
    asm volatile("ldmatrix.sync.aligned.m8n8.x4.shared.b16 {%0,%1,%2,%3}, [%4];"
        : "=r"(r[0]), "=r"(r[1]), "=r"(r[2]), "=r"(r[3]) : "r"(addr));
}
__device__ __forceinline__ void ldmx2(uint32_t* r, uint32_t addr) {
    asm volatile("ldmatrix.sync.aligned.m8n8.x2.shared.b16 {%0,%1}, [%2];"
        : "=r"(r[0]), "=r"(r[1]) : "r"(addr));
}
__device__ __forceinline__ void split2(float v, bf16& h, bf16& l) {
    h = __float2bfloat16(v);
    l = __float2bfloat16(v - __bfloat162float(h));
}
__device__ __forceinline__ uint32_t pack2(bf16 a, bf16 b) {
    __nv_bfloat162 t(a, b);
    return *(uint32_t*)&t;
}

// ---------------- split kernels ----------------
__global__ __launch_bounds__(256) void split_kernel(const float* __restrict__ x,
                                                    bf16* __restrict__ hi, bf16* __restrict__ lo, int n) {
    int i = blockIdx.x * 256 + threadIdx.x;
    if (i < n) { bf16 h, l; split2(x[i], h, l); hi[i] = h; lo[i] = l; }
}

__global__ __launch_bounds__(256) void tsplit_kernel(const float* __restrict__ W,
                                                     bf16* __restrict__ hi, bf16* __restrict__ lo,
                                                     int K, int N) {
    __shared__ float t[32][33];
    int n0 = blockIdx.x * 32, k0 = blockIdx.y * 32;
    int tx = threadIdx.x & 31, ty = threadIdx.x >> 5;
#pragma unroll
    for (int r = 0; r < 32; r += 8)
        t[ty + r][tx] = W[(size_t)(k0 + ty + r) * N + n0 + tx];
    __syncthreads();
#pragma unroll
    for (int r = 0; r < 32; r += 8) {
        float v = t[tx][ty + r];
        bf16 h, l; split2(v, h, l);
        size_t o = (size_t)(n0 + ty + r) * K + k0 + tx;
        hi[o] = h; lo[o] = l;
    }
}

__global__ __launch_bounds__(256) void rms_split_kernel(
    const float* __restrict__ x, const float* __restrict__ w,
    bf16* __restrict__ yh, bf16* __restrict__ yl) {
    __shared__ float red[256];
    int row = blockIdx.x;
    const float* xr = x + (size_t)row * DIM;
    float ss = 0.f;
    for (int c = threadIdx.x; c < DIM; c += 256) { float v = xr[c]; ss += v * v; }
    red[threadIdx.x] = ss; __syncthreads();
    for (int s = 128; s > 0; s >>= 1) {
        if (threadIdx.x < s) red[threadIdx.x] += red[threadIdx.x + s];
        __syncthreads();
    }
    float inv = rsqrtf(red[0] / (float)DIM + 1e-6f);
    for (int c = threadIdx.x; c < DIM; c += 256) {
        bf16 h, l; split2(xr[c] * inv * w[c], h, l);
        size_t o = (size_t)row * DIM + c;
        yh[o] = h; yl[o] = l;
    }
}

__global__ __launch_bounds__(256) void ln_split_kernel(
    const float* __restrict__ x, const float* __restrict__ g, const float* __restrict__ b,
    bf16* __restrict__ yh, bf16* __restrict__ yl) {
    __shared__ float r1[256], r2[256];
    int row = blockIdx.x;
    const float* xr = x + (size_t)row * DIM;
    float s1 = 0.f, s2 = 0.f;
    for (int c = threadIdx.x; c < DIM; c += 256) { float v = xr[c]; s1 += v; s2 += v * v; }
    r1[threadIdx.x] = s1; r2[threadIdx.x] = s2; __syncthreads();
    for (int s = 128; s > 0; s >>= 1) {
        if (threadIdx.x < s) { r1[threadIdx.x] += r1[threadIdx.x + s]; r2[threadIdx.x] += r2[threadIdx.x + s]; }
        __syncthreads();
    }
    float mu = r1[0] / (float)DIM;
    float rstd = rsqrtf(r2[0] / (float)DIM - mu * mu + 1e-5f);
    for (int c = threadIdx.x; c < DIM; c += 256) {
        bf16 h, l; split2((xr[c] - mu) * rstd * g[c] + b[c], h, l);
        size_t o = (size_t)row * DIM + c;
        yh[o] = h; yl[o] = l;
    }
}

// ---------------- mma.sync bf16x3 GEMM ----------------
// epi: 0: C=acc+bias | 1: C=res+tanh(g)*(acc+bias) | 2: gelu->split | 3: C=res+tanh(g)*acc
//      4: (acc+bias)*scale -> split (row-major) | 5: acc+bias -> split transposed (col*SKV+row)
#define RS    40
#define ARRB  10240
#define STGB  40960

__global__ __launch_bounds__(256) void gemm_mma(
    const bf16* __restrict__ Ahi, const bf16* __restrict__ Alo, long aStride,
    const bf16* __restrict__ Bhi, const bf16* __restrict__ Blo,
    const float* __restrict__ bias, const float* __restrict__ res, const float* __restrict__ gate,
    float* __restrict__ C, bf16* __restrict__ Chi, bf16* __restrict__ Clo,
    long cStride, int M, int N, int K, float scale, int epi)
{
    extern __shared__ __align__(128) char dsm[];

    int tid = threadIdx.x, wid = tid >> 5, lid = tid & 31;
    int wm = wid & 3, wn = wid >> 2;
    int m0 = blockIdx.y << 7, n0 = blockIdx.x << 7;

    Ahi += (size_t)blockIdx.z * aStride;
    Alo += (size_t)blockIdx.z * aStride;
    if (C) C += (size_t)blockIdx.z * cStride;
    if (Chi) { Chi += (size_t)blockIdx.z * cStride; Clo += (size_t)blockIdx.z * cStride; }

    uint32_t sbase = smem_u32(dsm);
    const bf16* aptr[4] = { Ahi + (size_t)m0 * K, Alo + (size_t)m0 * K,
                            Bhi + (size_t)n0 * K, Blo + (size_t)n0 * K };

    auto load_stage = [&](int k0, int st) {
        uint32_t base = sbase + (uint32_t)st * STGB;
#pragma unroll
        for (int i = 0; i < 8; i++) {
            int idx = tid + i * 256;
            int arr = idx >> 9;
            int rem = idx & 511;
            int row = rem >> 2;
            int ch  = rem & 3;
            uint32_t d = base + (uint32_t)arr * ARRB + (uint32_t)(row * RS * 2 + ch * 16);
            CP16(d, aptr[arr] + (size_t)row * K + k0 + ch * 8);
        }
    };

    float c[2][8][4];
#pragma unroll
    for (int mi = 0; mi < 2; mi++)
#pragma unroll
        for (int ni = 0; ni < 8; ni++)
#pragma unroll
            for (int r = 0; r < 4; r++) c[mi][ni][r] = 0.f;

    const int nt = K >> 5;
    load_stage(0, 0);
    CP_COMMIT();

    for (int t = 0; t < nt; t++) {
        int st = t & 1;
        if (t + 1 < nt) {
            load_stage((t + 1) << 5, st ^ 1);
            CP_COMMIT();
            CP_WAIT(1);
        } else {
            CP_WAIT(0);
        }
        __syncthreads();

        uint32_t Ah_b = sbase + (uint32_t)st * STGB;
        uint32_t Al_b = Ah_b + ARRB;
        uint32_t Bh_b = Ah_b + 2 * ARRB;
        uint32_t Bl_b = Ah_b + 3 * ARRB;

#pragma unroll
        for (int ks = 0; ks < 2; ks++) {
            int ko = ks * 16;
            uint32_t ah[2][4], al[2][4];
#pragma unroll
            for (int mi = 0; mi < 2; mi++) {
                uint32_t aoff = (uint32_t)((wm * 32 + mi * 16 + (lid & 15)) * RS + ko + ((lid >> 4) << 3)) * 2;
                ldmx4(ah[mi], Ah_b + aoff);
                ldmx4(al[mi], Al_b + aoff);
            }
#pragma unroll
            for (int nh2 = 0; nh2 < 2; nh2++) {
                uint32_t bh[4][2], bl[4][2];
#pragma unroll
                for (int nj = 0; nj < 4; nj++) {
                    uint32_t boff = (uint32_t)((wn * 64 + (nh2 * 4 + nj) * 8 + (lid & 7)) * RS
                                               + ko + (((lid >> 3) & 1) << 3)) * 2;
                    ldmx2(bh[nj], Bh_b + boff);
                    ldmx2(bl[nj], Bl_b + boff);
                }
#pragma unroll
                for (int mi = 0; mi < 2; mi++)
#pragma unroll
                    for (int nj = 0; nj < 4; nj++) {
                        float* cc = c[mi][nh2 * 4 + nj];
                        mma_bf16(cc, ah[mi], bh[nj]);
                        mma_bf16(cc, ah[mi], bl[nj]);
                        mma_bf16(cc, al[mi], bh[nj]);
                    }
            }
        }
        __syncthreads();
    }

    float gv = (epi == 1 || epi == 3) ? tanhf(*gate) : 0.f;
#pragma unroll
    for (int mi = 0; mi < 2; mi++) {
#pragma unroll
        for (int ni = 0; ni < 8; ni++) {
            int col = n0 + wn * 64 + ni * 8 + (lid & 3) * 2;
            float bcol0 = 0.f, bcol1 = 0.f;
            if (epi == 0 || epi == 1 || epi == 4 || epi == 5) { bcol0 = bias[col]; bcol1 = bias[col + 1]; }
#pragma unroll
            for (int rh = 0; rh < 2; rh++) {
                int m = m0 + wm * 32 + mi * 16 + (lid >> 2) + rh * 8;
                float v0 = c[mi][ni][rh * 2 + 0];
                float v1 = c[mi][ni][rh * 2 + 1];
                if (epi == 5) {
                    bf16 h, l;
                    split2(v0 + bcol0, h, l);
                    Chi[(size_t)col * SKV + m] = h; Clo[(size_t)col * SKV + m] = l;
                    split2(v1 + bcol1, h, l);
                    Chi[(size_t)(col + 1) * SKV + m] = h; Clo[(size_t)(col + 1) * SKV + m] = l;
                    continue;
                }
                size_t o = (size_t)m * N + col;
                if (epi == 0) {
                    C[o] = v0 + bcol0; C[o + 1] = v1 + bcol1;
                } else if (epi == 1) {
                    C[o]     = res[o]     + gv * (v0 + bcol0);
                    C[o + 1] = res[o + 1] + gv * (v1 + bcol1);
                } else if (epi == 2) {
                    float g0 = 0.5f * v0 * (1.f + erff(v0 * 0.70710678118654752f));
                    float g1 = 0.5f * v1 * (1.f + erff(v1 * 0.70710678118654752f));
                    bf16 h0, l0, h1, l1;
                    split2(g0, h0, l0); split2(g1, h1, l1);
                    *(uint32_t*)&Chi[o] = pack2(h0, h1);
                    *(uint32_t*)&Clo[o] = pack2(l0, l1);
                } else if (epi == 3) {
                    C[o]     = res[o]     + gv * v0;
                    C[o + 1] = res[o + 1] + gv * v1;
                } else { // epi == 4
                    bf16 h0, l0, h1, l1;
                    split2((v0 + bcol0) * scale, h0, l0);
                    split2((v1 + bcol1) * scale, h1, l1);
                    *(uint32_t*)&Chi[o] = pack2(h0, h1);
                    *(uint32_t*)&Clo[o] = pack2(l0, l1);
                }
            }
        }
    }
}

// ---------------- tensor-core flash attention ----------------
// Br=128 (8 warps x 16 rows), Bc=64, HD=128, 3-term hi/lo split throughout.
#define AQH 0
#define AQL 17408
#define AKH(st) (34816 + (st) * 17408)
#define AKL(st) (AKH(st) + 8704)
#define AVH(st) (69632 + (st) * 18432)
#define AVL(st) (AVH(st) + 9216)
#define AMSK_BYTES 212992
#define ATT_SMEM (AMSK_BYTES + 512)
#define NKT (SKV / 64)

__global__ __launch_bounds__(256) void attn_tc(
    const bf16* __restrict__ qh, const bf16* __restrict__ ql,
    const bf16* __restrict__ kh, const bf16* __restrict__ kl,
    const bf16* __restrict__ vth, const bf16* __restrict__ vtl,
    const float* __restrict__ qmask, const float* __restrict__ pmask,
    const float* __restrict__ smask, const float* __restrict__ mmask,
    bf16* __restrict__ ch, bf16* __restrict__ cl)
{
    extern __shared__ __align__(128) char dsm[];
    uint32_t sb = smem_u32(dsm);

    int b = blockIdx.z, h = blockIdx.y, q0 = blockIdx.x * 128;
    int tid = threadIdx.x, wid = tid >> 5, lid = tid & 31;
    int wr = wid * 16;

    // Q prologue load (hi+lo): 4096 x 16B chunks
#pragma unroll
    for (int i = 0; i < 16; i++) {
        int idx = tid + i * 256;
        int grp = idx >> 11;
        int rem = idx & 2047;
        int r = rem >> 4, cch = rem & 15;
        const bf16* src = (grp ? ql : qh) + (size_t)(b * SQL + q0 + r) * DIM + h * HD + cch * 8;
        uint32_t dst = sb + (uint32_t)((grp ? AQL : AQH) + r * 136 + cch * 8) * 2;
        CP16(dst, src);
    }

    auto load_stage = [&](int kt, int st) {
#pragma unroll
        for (int i = 0; i < 16; i++) {
            int idx = tid + i * 256;
            int grp = idx >> 10;
            int rem = idx & 1023;
            if (grp < 2) {
                int r = rem >> 4, cch = rem & 15;
                const bf16* src = (grp == 0 ? kh : kl) + (size_t)(b * SKV + kt + r) * DIM + h * HD + cch * 8;
                uint32_t dst = sb + (uint32_t)((grp == 0 ? AKH(st) : AKL(st)) + r * 136 + cch * 8) * 2;
                CP16(dst, src);
            } else {
                int r = rem >> 3, cch = rem & 7;
                const bf16* src = (grp == 2 ? vth : vtl) + (size_t)b * DIM * SKV + (size_t)(h * HD + r) * SKV + kt + cch * 8;
                uint32_t dst = sb + (uint32_t)((grp == 2 ? AVH(st) : AVL(st)) + r * 72 + cch * 8) * 2;
                CP16(dst, src);
            }
        }
        if (tid < 64) {
            int kidx = kt + tid;
            const float* srcm;
            if (kidx < SP)           srcm = pmask + b * SP + kidx;
            else if (kidx < SP + SS) srcm = smask + b * SS + (kidx - SP);
            else                     srcm = mmask + b * SMm + (kidx - SP - SS);
            CP4(sb + AMSK_BYTES + st * 256 + tid * 4, srcm);
        }
    };

    float qm2[2];
    qm2[0] = qmask[b * SQL + q0 + wr + (lid >> 2)];
    qm2[1] = qmask[b * SQL + q0 + wr + (lid >> 2) + 8];

    float m2[2] = { -1e30f, -1e30f }, l2[2] = { 0.f, 0.f };
    float o[16][4];
#pragma unroll
    for (int ni = 0; ni < 16; ni++)
#pragma unroll
        for (int r = 0; r < 4; r++) o[ni][r] = 0.f;

    load_stage(0, 0);
    CP_COMMIT();

    for (int t = 0; t < NKT; t++) {
        int st = t & 1;
        CP_WAIT(0);
        __syncthreads();
        if (t + 1 < NKT) { load_stage((t + 1) * 64, st ^ 1); CP_COMMIT(); }

        // ---- S = Qh*Kh + Qh*Kl + Ql*Kh ----
        float cs[8][4];
#pragma unroll
        for (int ni = 0; ni < 8; ni++)
#pragma unroll
            for (int r = 0; r < 4; r++) cs[ni][r] = 0.f;

        uint32_t akh = sb + (uint32_t)AKH(st) * 2;
        uint32_t akl = sb + (uint32_t)AKL(st) * 2;
#pragma unroll
        for (int ko = 0; ko < 8; ko++) {
            uint32_t aoff = (uint32_t)((wr + (lid & 15)) * 136 + ko * 16 + ((lid >> 4) << 3)) * 2;
            uint32_t aqh[4], aql[4];
            ldmx4(aqh, sb + AQH * 2 + aoff);
            ldmx4(aql, sb + (uint32_t)AQL * 2 + aoff);
#pragma unroll
            for (int ni = 0; ni < 8; ni++) {
                uint32_t boff = (uint32_t)((ni * 8 + (lid & 7)) * 136 + ko * 16 + (((lid >> 3) & 1) << 3)) * 2;
                uint32_t bh[2], bl[2];
                ldmx2(bh, akh + boff);
                ldmx2(bl, akl + boff);
                mma_bf16(cs[ni], aqh, bh);
                mma_bf16(cs[ni], aqh, bl);
                mma_bf16(cs[ni], aql, bh);
            }
        }

        // ---- mask + online softmax ----
        const float* kmf = (const float*)(dsm + AMSK_BYTES + st * 256);
#pragma unroll
        for (int ni = 0; ni < 8; ni++) {
            int c0 = ni * 8 + (lid & 3) * 2;
            float km0 = kmf[c0], km1 = kmf[c0 + 1];
            if (qm2[0] == 0.f || km0 == 0.f) cs[ni][0] = -1e30f;
            if (qm2[0] == 0.f || km1 == 0.f) cs[ni][1] = -1e30f;
            if (qm2[1] == 0.f || km0 == 0.f) cs[ni][2] = -1e30f;
            if (qm2[1] == 0.f || km1 == 0.f) cs[ni][3] = -1e30f;
        }
#pragma unroll
        for (int rh = 0; rh < 2; rh++) {
            float mt = -1e30f;
#pragma unroll
            for (int ni = 0; ni < 8; ni++)
                mt = fmaxf(mt, fmaxf(cs[ni][rh * 2], cs[ni][rh * 2 + 1]));
            mt = fmaxf(mt, __shfl_xor_sync(0xffffffffu, mt, 1));
            mt = fmaxf(mt, __shfl_xor_sync(0xffffffffu, mt, 2));
            float nm = fmaxf(m2[rh], mt);
            float al = __expf(m2[rh] - nm);
            float ps = 0.f;
#pragma unroll
            for (int ni = 0; ni < 8; ni++) {
                float p0 = __expf(cs[ni][rh * 2] - nm);
                float p1 = __expf(cs[ni][rh * 2 + 1] - nm);
                cs[ni][rh * 2] = p0; cs[ni][rh * 2 + 1] = p1;
                ps += p0 + p1;
            }
            ps += __shfl_xor_sync(0xffffffffu, ps, 1);
            ps += __shfl_xor_sync(0xffffffffu, ps, 2);
            l2[rh] = l2[rh] * al + ps;
            m2[rh] = nm;
#pragma unroll
            for (int ni = 0; ni < 16; ni++) {
                o[ni][rh * 2] *= al; o[ni][rh * 2 + 1] *= al;
            }
        }

        // ---- PV: O += Ph*Vh + Ph*Vl + Pl*Vh ----
        uint32_t avh = sb + (uint32_t)AVH(st) * 2;
        uint32_t avl = sb + (uint32_t)AVL(st) * 2;
#pragma unroll
        for (int kk = 0; kk < 4; kk++) {
            int t0 = 2 * kk, t1 = 2 * kk + 1;
            uint32_t pah[4], pal[4];
            {
                bf16 h00, l00, h01, l01, h10, l10, h11, l11;
                split2(cs[t0][0], h00, l00); split2(cs[t0][1], h01, l01);
                split2(cs[t0][2], h10, l10); split2(cs[t0][3], h11, l11);
                pah[0] = pack2(h00, h01); pal[0] = pack2(l00, l01);
                pah[1] = pack2(h10, h11); pal[1] = pack2(l10, l11);
                split2(cs[t1][0], h00, l00); split2(cs[t1][1], h01, l01);
                split2(cs[t1][2], h10, l10); split2(cs[t1][3], h11, l11);
                pah[2] = pack2(h00, h01); pal[2] = pack2(l00, l01);
                pah[3] = pack2(h10, h11); pal[3] = pack2(l10, l11);
            }
#pragma unroll
            for (int ni = 0; ni < 16; ni++) {
                uint32_t boff = (uint32_t)((ni * 8 + (lid & 7)) * 72 + kk * 16 + (((lid >> 3) & 1) << 3)) * 2;
                uint32_t bvh[2], bvl[2];
                ldmx2(bvh, avh + boff);
                ldmx2(bvl, avl + boff);
                mma_bf16(o[ni], pah, bvh);
                mma_bf16(o[ni], pah, bvl);
                mma_bf16(o[ni], pal, bvh);
            }
        }
    }

    // ---- epilogue: o/l -> split bf16 ----
#pragma unroll
    for (int rh = 0; rh < 2; rh++) {
        float inv = 1.f / l2[rh];
        int row = q0 + wr + (lid >> 2) + rh * 8;
#pragma unroll
        for (int ni = 0; ni < 16; ni++) {
            int col = h * HD + ni * 8 + (lid & 3) * 2;
            size_t off = (size_t)(b * SQL + row) * DIM + col;
            bf16 h0, l0, h1, l1;
            split2(o[ni][rh * 2] * inv, h0, l0);
            split2(o[ni][rh * 2 + 1] * inv, h1, l1);
            *(uint32_t*)&ch[off] = pack2(h0, h1);
            *(uint32_t*)&cl[off] = pack2(l0, l1);
        }
    }
}

// ---------------- launch ----------------
extern "C" void kernel_launch(void* const* d_in, const int* in_sizes, int n_in,
                              void* d_out, int out_size)
{
    const float* x   = (const float*)d_in[0];
    const float* pkv = (const float*)d_in[1];
    const float* skv = (const float*)d_in[2];
    const float* mkv = (const float*)d_in[3];
    const float* qm  = (const float*)d_in[4];
    const float* pm  = (const float*)d_in[5];
    const float* smk = (const float*)d_in[6];
    const float* mmk = (const float*)d_in[7];
    const float* rw  = (const float*)d_in[8];
    const float* Wq  = (const float*)d_in[9];
    const float* bq  = (const float*)d_in[10];
    const float* Wkp = (const float*)d_in[11];
    const float* bkp = (const float*)d_in[12];
    const float* Wvp = (const float*)d_in[13];
    const float* bvp = (const float*)d_in[14];
    const float* Wks = (const float*)d_in[15];
    const float* bks = (const float*)d_in[16];
    const float* Wvs = (const float*)d_in[17];
    const float* bvs = (const float*)d_in[18];
    const float* Wkm = (const float*)d_in[19];
    const float* bkm = (const float*)d_in[20];
    const float* Wvm = (const float*)d_in[21];
    const float* bvm = (const float*)d_in[22];
    const float* Wo  = (const float*)d_in[23];
    const float* bo  = (const float*)d_in[24];
    const float* lg  = (const float*)d_in[25];
    const float* lb  = (const float*)d_in[26];
    const float* W1  = (const float*)d_in[27];
    const float* W2  = (const float*)d_in[28];
    const float* ga  = (const float*)d_in[29];
    const float* gf  = (const float*)d_in[30];
    float* out = (float*)d_out;

    float* hb;
    cudaGetSymbolAddress((void**)&hb, g_h);

    bf16 *xnh, *xnl, *pkh, *pkl, *skh, *skl, *mkh, *mkl, *cth, *ctl, *lnh, *lnl, *mdh, *mdl;
    cudaGetSymbolAddress((void**)&xnh, g_xnh); cudaGetSymbolAddress((void**)&xnl, g_xnl);
    cudaGetSymbolAddress((void**)&pkh, g_pkh); cudaGetSymbolAddress((void**)&pkl, g_pkl);
    cudaGetSymbolAddress((void**)&skh, g_skh); cudaGetSymbolAddress((void**)&skl, g_skl);
    cudaGetSymbolAddress((void**)&mkh, g_mkh); cudaGetSymbolAddress((void**)&mkl, g_mkl);
    cudaGetSymbolAddress((void**)&cth, g_cth); cudaGetSymbolAddress((void**)&ctl, g_ctl);
    cudaGetSymbolAddress((void**)&lnh, g_lnh); cudaGetSymbolAddress((void**)&lnl, g_lnl);
    cudaGetSymbolAddress((void**)&mdh, g_mdh); cudaGetSymbolAddress((void**)&mdl, g_mdl);

    bf16 *qh, *ql, *kh, *kl, *vth, *vtl;
    cudaGetSymbolAddress((void**)&qh, g_qh);   cudaGetSymbolAddress((void**)&ql, g_ql);
    cudaGetSymbolAddress((void**)&kh, g_kh2);  cudaGetSymbolAddress((void**)&kl, g_kl2);
    cudaGetSymbolAddress((void**)&vth, g_vth); cudaGetSymbolAddress((void**)&vtl, g_vtl);

    bf16 *wqh, *wql, *kph, *kpl, *vph, *vpl, *ksh, *ksl, *vsh, *vsl, *kmh, *kml, *vmh, *vml, *woh, *wol, *w1h, *w1l, *w2h, *w2l;
    cudaGetSymbolAddress((void**)&wqh, g_wqh); cudaGetSymbolAddress((void**)&wql, g_wql);
    cudaGetSymbolAddress((void**)&kph, g_kph); cudaGetSymbolAddress((void**)&kpl, g_kpl);
    cudaGetSymbolAddress((void**)&vph, g_vph); cudaGetSymbolAddress((void**)&vpl, g_vpl);
    cudaGetSymbolAddress((void**)&ksh, g_ksh); cudaGetSymbolAddress((void**)&ksl, g_ksl);
    cudaGetSymbolAddress((void**)&vsh, g_vsh); cudaGetSymbolAddress((void**)&vsl, g_vsl);
    cudaGetSymbolAddress((void**)&kmh, g_kmh); cudaGetSymbolAddress((void**)&kml, g_kml);
    cudaGetSymbolAddress((void**)&vmh, g_vmh); cudaGetSymbolAddress((void**)&vml, g_vml);
    cudaGetSymbolAddress((void**)&woh, g_woh); cudaGetSymbolAddress((void**)&wol, g_wol);
    cudaGetSymbolAddress((void**)&w1h, g_w1h); cudaGetSymbolAddress((void**)&w1l, g_w1l);
    cudaGetSymbolAddress((void**)&w2h, g_w2h); cudaGetSymbolAddress((void**)&w2l, g_w2l);

    size_t gemm_sh = 2 * STGB;
    cudaFuncSetAttribute(gemm_mma, cudaFuncAttributeMaxDynamicSharedMemorySize, (int)gemm_sh);
    cudaFuncSetAttribute(attn_tc, cudaFuncAttributeMaxDynamicSharedMemorySize, ATT_SMEM);

    // 1) weight transpose + split
    tsplit_kernel<<<dim3(DIM / 32, DIM / 32),  256>>>(Wq,  wqh, wql, DIM,   DIM);
    tsplit_kernel<<<dim3(DIM / 32, DP / 32),   256>>>(Wkp, kph, kpl, DP,    DIM);
    tsplit_kernel<<<dim3(DIM / 32, DP / 32),   256>>>(Wvp, vph, vpl, DP,    DIM);
    tsplit_kernel<<<dim3(DIM / 32, DS / 32),   256>>>(Wks, ksh, ksl, DS,    DIM);
    tsplit_kernel<<<dim3(DIM / 32, DS / 32),   256>>>(Wvs, vsh, vsl, DS,    DIM);
    tsplit_kernel<<<dim3(DIM / 32, DMm / 32),  256>>>(Wkm, kmh, kml, DMm,   DIM);
    tsplit_kernel<<<dim3(DIM / 32, DMm / 32),  256>>>(Wvm, vmh, vml, DMm,   DIM);
    tsplit_kernel<<<dim3(DIM / 32, DIM / 32),  256>>>(Wo,  woh, wol, DIM,   DIM);
    tsplit_kernel<<<dim3(INNER / 32, DIM / 32), 256>>>(W1, w1h, w1l, DIM,   INNER);
    tsplit_kernel<<<dim3(DIM / 32, INNER / 32), 256>>>(W2, w2h, w2l, INNER, DIM);

    // 2) activation splits
    rms_split_kernel<<<BN * SQL, 256>>>(x, rw, xnh, xnl);
    split_kernel<<<(BN * SP * DP) / 256,   256>>>(pkv, pkh, pkl, BN * SP * DP);
    split_kernel<<<(BN * SS * DS) / 256,   256>>>(skv, skh, skl, BN * SS * DS);
    split_kernel<<<(BN * SMm * DMm) / 256, 256>>>(mkv, mkh, mkl, BN * SMm * DMm);

    // 3) projections: Q (scaled 0.25, split), K (split), V (split transposed)
    gemm_mma<<<dim3(DIM / 128, 16, 1), 256, gemm_sh>>>(xnh, xnl, 0, wqh, wql, bq, nullptr, nullptr,
        nullptr, qh, ql, 0, BN * SQL, DIM, DIM, 0.25f, 4);
    gemm_mma<<<dim3(DIM / 128, SP / 128, BN), 256, gemm_sh>>>(pkh, pkl, (long)SP * DP, kph, kpl, bkp, nullptr, nullptr,
        nullptr, kh, kl, (long)SKV * DIM, SP, DIM, DP, 1.f, 4);
    gemm_mma<<<dim3(DIM / 128, SS / 128, BN), 256, gemm_sh>>>(skh, skl, (long)SS * DS, ksh, ksl, bks, nullptr, nullptr,
        nullptr, kh + (size_t)SP * DIM, kl + (size_t)SP * DIM, (long)SKV * DIM, SS, DIM, DS, 1.f, 4);
    gemm_mma<<<dim3(DIM / 128, SMm / 128, BN), 256, gemm_sh>>>(mkh, mkl, (long)SMm * DMm, kmh, kml, bkm, nullptr, nullptr,
        nullptr, kh + (size_t)(SP + SS) * DIM, kl + (size_t)(SP + SS) * DIM, (long)SKV * DIM, SMm, DIM, DMm, 1.f, 4);
    gemm_mma<<<dim3(DIM / 128, SP / 128, BN), 256, gemm_sh>>>(pkh, pkl, (long)SP * DP, vph, vpl, bvp, nullptr, nullptr,
        nullptr, vth, vtl, (long)DIM * SKV, SP, DIM, DP, 1.f, 5);
    gemm_mma<<<dim3(DIM / 128, SS / 128, BN), 256, gemm_sh>>>(skh, skl, (long)SS * DS, vsh, vsl, bvs, nullptr, nullptr,
        nullptr, vth + SP, vtl + SP, (long)DIM * SKV, SS, DIM, DS, 1.f, 5);
    gemm_mma<<<dim3(DIM / 128, SMm / 128, BN), 256, gemm_sh>>>(mkh, mkl, (long)SMm * DMm, vmh, vml, bvm, nullptr, nullptr,
        nullptr, vth + (SP + SS), vtl + (SP + SS), (long)DIM * SKV, SMm, DIM, DMm, 1.f, 5);

    // 4) tensor-core flash attention -> ctx split
    attn_tc<<<dim3(SQL / 128, NH, BN), 256, ATT_SMEM>>>(qh, ql, kh, kl, vth, vtl,
                                                        qm, pm, smk, mmk, cth, ctl);

    // 5) Wo projection + gated residual
    gemm_mma<<<dim3(DIM / 128, 16, 1), 256, gemm_sh>>>(cth, ctl, 0, woh, wol, bo, x, ga,
        hb, nullptr, nullptr, 0, BN * SQL, DIM, DIM, 1.f, 1);

    // 6) LayerNorm -> split
    ln_split_kernel<<<BN * SQL, 256>>>(hb, lg, lb, lnh, lnl);

    // 7) FFW up + GELU -> split
    gemm_mma<<<dim3(INNER / 128, 16, 1), 256, gemm_sh>>>(lnh, lnl, 0, w1h, w1l, nullptr, nullptr, nullptr,
        nullptr, mdh, mdl, 0, BN * SQL, INNER, DIM, 1.f, 2);

    // 8) FFW down + gated residual -> out
    gemm_mma<<<dim3(DIM / 128, 16, 1), 256, gemm_sh>>>(mdh, mdl, 0, w2h, w2l, nullptr, hb, gf,
        out, nullptr, nullptr, 0, BN * SQL, DIM, INNER, 1.f, 3);
}